// round 3
// baseline (speedup 1.0000x reference)
#include <cuda_runtime.h>
#include <mma.h>
using namespace nvcuda;

// Problem dims
constexpr int kB = 64;      // batch
constexpr int kT = 512;     // seq len
constexpr int kE = 512;     // embed
constexpr int kH = 1024;    // hidden
constexpr int kBT = kB * kT;           // 32768
constexpr int k3H = 3 * kH;            // 3072
constexpr size_t kXPSZ = (size_t)kBT * k3H;       // per-dir xp elements
constexpr size_t kOUTSZ = (size_t)kBT * 2 * kH;   // outputs elements

// Scratch (device globals are the sanctioned scratch mechanism)
__device__ float g_emb[(size_t)kBT * kE];   // 64 MB
__device__ float g_xp[2 * kXPSZ];           // 805 MB, fwd then bwd
__device__ float g_h[2][2][kB * kH];        // [parity][dir][B*H]
__device__ unsigned int g_bar[2];           // per-dir step barrier counters

// ---------------------------------------------------------------------------
__global__ void zero_h_kernel() {
    int idx = blockIdx.x * blockDim.x + threadIdx.x;  // 262144 total
    ((float*)g_h)[idx] = 0.0f;
    if (blockIdx.x == 0 && threadIdx.x < 2) g_bar[threadIdx.x] = 0u;
}

// emb[m, :] = embed_W[seqs[m], :]
__global__ void gather_kernel(const int* __restrict__ seqs,
                              const float* __restrict__ embW) {
    int m = blockIdx.x;
    int t4 = threadIdx.x;  // 128 threads, E/4 float4 per row
    int row = seqs[m];
    reinterpret_cast<float4*>(g_emb)[(size_t)m * (kE / 4) + t4] =
        reinterpret_cast<const float4*>(embW)[(size_t)row * (kE / 4) + t4];
}

// ---------------------------------------------------------------------------
// xp = emb @ W_ih^T + b_ih for both directions.
// Block tile M=128, N=64, K-chunk 16. 8 warps (4x2), warp tile 32x32.
__global__ void xp_gemm_kernel(const float* __restrict__ Wf,
                               const float* __restrict__ Wb,
                               const float* __restrict__ bf,
                               const float* __restrict__ bb) {
    constexpr int BM = 128, BN = 64, BK = 16, BKP = 20;
    __shared__ float As[BM][BKP];
    __shared__ float Bs[BN][BKP];
    __shared__ float Cs[8][32][32];

    int dir = blockIdx.z;
    const float* W = dir ? Wb : Wf;
    const float* bias = dir ? bb : bf;
    float* xp = g_xp + (size_t)dir * kXPSZ;

    int m0 = blockIdx.y * BM, n0 = blockIdx.x * BN;
    int tid = threadIdx.x, wid = tid >> 5, lane = tid & 31;
    int wm = wid >> 1, wn = wid & 1;

    wmma::fragment<wmma::accumulator, 16, 16, 8, float> acc[2][2];
#pragma unroll
    for (int i = 0; i < 2; i++)
#pragma unroll
        for (int j = 0; j < 2; j++) wmma::fill_fragment(acc[i][j], 0.0f);

    for (int k0 = 0; k0 < kE; k0 += BK) {
#pragma unroll
        for (int it = 0; it < 2; it++) {
            int i = tid + it * 256;
            int r = i >> 2, c4 = i & 3;
            float4 v = *reinterpret_cast<const float4*>(
                &g_emb[(size_t)(m0 + r) * kE + k0 + c4 * 4]);
            *reinterpret_cast<float4*>(&As[r][c4 * 4]) = v;
        }
        {
            int r = tid >> 2, c4 = tid & 3;
            float4 v = *reinterpret_cast<const float4*>(
                &W[(size_t)(n0 + r) * kE + k0 + c4 * 4]);
            *reinterpret_cast<float4*>(&Bs[r][c4 * 4]) = v;
        }
        __syncthreads();
#pragma unroll
        for (int kk = 0; kk < BK; kk += 8) {
            wmma::fragment<wmma::matrix_a, 16, 16, 8, wmma::precision::tf32,
                           wmma::row_major> a[2];
            wmma::fragment<wmma::matrix_b, 16, 16, 8, wmma::precision::tf32,
                           wmma::col_major> b[2];
            wmma::load_matrix_sync(a[0], &As[wm * 32][kk], BKP);
            wmma::load_matrix_sync(a[1], &As[wm * 32 + 16][kk], BKP);
            wmma::load_matrix_sync(b[0], &Bs[wn * 32][kk], BKP);
            wmma::load_matrix_sync(b[1], &Bs[wn * 32 + 16][kk], BKP);
#pragma unroll
            for (int i = 0; i < 2; i++) {
#pragma unroll
                for (int e = 0; e < a[i].num_elements; e++)
                    a[i].x[e] = wmma::__float_to_tf32(a[i].x[e]);
#pragma unroll
                for (int e = 0; e < b[i].num_elements; e++)
                    b[i].x[e] = wmma::__float_to_tf32(b[i].x[e]);
            }
#pragma unroll
            for (int i = 0; i < 2; i++)
#pragma unroll
                for (int j = 0; j < 2; j++)
                    wmma::mma_sync(acc[i][j], a[i], b[j], acc[i][j]);
        }
        __syncthreads();
    }
#pragma unroll
    for (int i = 0; i < 2; i++)
#pragma unroll
        for (int j = 0; j < 2; j++)
            wmma::store_matrix_sync(&Cs[wid][i * 16][j * 16], acc[i][j], 32,
                                    wmma::mem_row_major);
    __syncwarp();
    int gm = m0 + wm * 32, gn = n0 + wn * 32;
    float bv = bias[gn + lane];
#pragma unroll
    for (int r = 0; r < 32; r++) {
        xp[(size_t)(gm + r) * k3H + gn + lane] = Cs[wid][r][lane] + bv;
    }
}

// ---------------------------------------------------------------------------
// Persistent GRU recurrence: ONE launch runs all 512 steps for both dirs.
// 128 blocks (64/dir), each owns 16 hidden cols -> 48 gate rows of W_hh,
// kept resident in SMEM (pre-rounded to tf32). Per step: GEMM
// M=64 x N=48 x K=1024 with double-buffered hprev chunks, fused gates,
// then a per-direction global barrier.
constexpr int WS_ST = 1032;                       // 1024 + 8 pad (bank-safe)
constexpr int AS_ST = 40;                         // 32 + 8 pad
constexpr int SM_WS = 48 * WS_ST;                 // 49536 floats
constexpr int SM_AS = 2 * kB * AS_ST;             // 5120 floats
constexpr int SM_CS = kB * 48;                    // 3072 floats
constexpr int SM_TOTAL_FLOATS = SM_WS + SM_AS + SM_CS + 48;
constexpr size_t SM_BYTES = (size_t)SM_TOTAL_FLOATS * 4;  // 231104 B

__global__ void __launch_bounds__(384, 1)
step_persist_kernel(const float* __restrict__ Whf,
                    const float* __restrict__ Whb,
                    const float* __restrict__ bhf,
                    const float* __restrict__ bhb,
                    float* __restrict__ out) {
    extern __shared__ float sm[];
    float* Ws = sm;                   // [48][WS_ST]  W slice, tf32-rounded
    float* As = sm + SM_WS;           // [2][64][AS_ST] hprev chunks
    float* Cs = sm + SM_WS + SM_AS;   // [64][48] gate pre-activations
    float* bsl = Cs + SM_CS;          // [48] bias slice

    int bx = blockIdx.x;
    int dir = bx >> 6;
    int j0 = (bx & 63) * 16;
    const float* W = dir ? Whb : Whf;
    const float* bhh = dir ? bhb : bhf;
    const float* xp = g_xp + (size_t)dir * kXPSZ;

    int tid = threadIdx.x, wid = tid >> 5;
    int g = wid >> 2;      // gate 0..2
    int mt = wid & 3;      // m-tile 0..3

    // ---- preload W slice (48 rows x 1024) into SMEM, rounded to tf32 ----
    for (int i = tid; i < 48 * 256; i += 384) {
        int r = i >> 8, c4 = i & 255;
        int wrow = (r >> 4) * kH + j0 + (r & 15);
        float4 v = *reinterpret_cast<const float4*>(
            &W[(size_t)wrow * kH + c4 * 4]);
        v.x = wmma::__float_to_tf32(v.x);
        v.y = wmma::__float_to_tf32(v.y);
        v.z = wmma::__float_to_tf32(v.z);
        v.w = wmma::__float_to_tf32(v.w);
        *reinterpret_cast<float4*>(&Ws[r * WS_ST + c4 * 4]) = v;
    }
    if (tid < 48) bsl[tid] = bhh[(tid >> 4) * kH + j0 + (tid & 15)];
    __syncthreads();

    for (int s = 0; s < kT; s++) {
        int parity = s & 1;
        const float* hprev = g_h[parity][dir];
        float* hnext = g_h[parity ^ 1][dir];
        int t_idx = dir ? (kT - 1 - s) : s;

        wmma::fragment<wmma::accumulator, 16, 16, 8, float> acc;
        wmma::fill_fragment(acc, 0.0f);

        // prefetch chunk 0 (64 x 32 floats = 512 float4)
        for (int i = tid; i < 512; i += 384) {
            int r = i >> 3, c4 = i & 7;
            float4 v = *reinterpret_cast<const float4*>(
                &hprev[(size_t)r * kH + c4 * 4]);
            v.x = wmma::__float_to_tf32(v.x);
            v.y = wmma::__float_to_tf32(v.y);
            v.z = wmma::__float_to_tf32(v.z);
            v.w = wmma::__float_to_tf32(v.w);
            *reinterpret_cast<float4*>(&As[r * AS_ST + c4 * 4]) = v;
        }
        __syncthreads();

        for (int kc = 0; kc < 32; kc++) {
            int cur = kc & 1;
            if (kc < 31) {
                float* dst = &As[(cur ^ 1) * kB * AS_ST];
                int kbase = (kc + 1) * 32;
                for (int i = tid; i < 512; i += 384) {
                    int r = i >> 3, c4 = i & 7;
                    float4 v = *reinterpret_cast<const float4*>(
                        &hprev[(size_t)r * kH + kbase + c4 * 4]);
                    v.x = wmma::__float_to_tf32(v.x);
                    v.y = wmma::__float_to_tf32(v.y);
                    v.z = wmma::__float_to_tf32(v.z);
                    v.w = wmma::__float_to_tf32(v.w);
                    *reinterpret_cast<float4*>(&dst[r * AS_ST + c4 * 4]) = v;
                }
            }
            const float* abuf = &As[cur * kB * AS_ST];
#pragma unroll
            for (int kk = 0; kk < 32; kk += 8) {
                wmma::fragment<wmma::matrix_a, 16, 16, 8,
                               wmma::precision::tf32, wmma::row_major> a;
                wmma::fragment<wmma::matrix_b, 16, 16, 8,
                               wmma::precision::tf32, wmma::col_major> b;
                wmma::load_matrix_sync(a, &abuf[(mt * 16) * AS_ST + kk], AS_ST);
                wmma::load_matrix_sync(b, &Ws[(g * 16) * WS_ST + kc * 32 + kk],
                                       WS_ST);
                wmma::mma_sync(acc, a, b, acc);
            }
            __syncthreads();
        }
        wmma::store_matrix_sync(&Cs[(mt * 16) * 48 + g * 16], acc, 48,
                                wmma::mem_row_major);
        __syncthreads();

        // gate fusion + h update + output write
        for (int idx = tid; idx < kB * 16; idx += 384) {
            int b = idx >> 4, jj = idx & 15, j = j0 + jj;
            size_t mrow = (size_t)(b * kT + t_idx);
            const float* xpr = xp + mrow * k3H;
            float xr = xpr[j], xz = xpr[kH + j], xn = xpr[2 * kH + j];
            float ghr = Cs[b * 48 + jj] + bsl[jj];
            float ghz = Cs[b * 48 + 16 + jj] + bsl[16 + jj];
            float ghn = Cs[b * 48 + 32 + jj] + bsl[32 + jj];
            float r = 1.0f / (1.0f + __expf(-(xr + ghr)));
            float z = 1.0f / (1.0f + __expf(-(xz + ghz)));
            float n = tanhf(xn + r * ghn);
            float hp = hprev[b * kH + j];
            float hv = (1.0f - z) * n + z * hp;
            hnext[b * kH + j] = hv;
            out[mrow * (2 * kH) + dir * kH + j] = hv;
        }

        // per-direction global barrier (monotone counter, no reset)
        __threadfence();
        __syncthreads();
        if (tid == 0) {
            atomicAdd(&g_bar[dir], 1u);
            unsigned target = 64u * (unsigned)(s + 1);
            while (atomicAdd(&g_bar[dir], 0u) < target) __nanosleep(64);
            __threadfence();
        }
        __syncthreads();
    }
}

// ---------------------------------------------------------------------------
// hiddens = tanh([h_f, h_b] @ fc_W^T + fc_b). Final states live in g_h[0][*].
__global__ void fc_kernel(const float* __restrict__ fcW,
                          const float* __restrict__ fcb,
                          float* __restrict__ out) {
    __shared__ float hc[2 * kH];
    int b = blockIdx.y;
    int tid = threadIdx.x, wid = tid >> 5, lane = tid & 31;
    for (int i = tid; i < (2 * kH) / 4; i += 256) {
        int k = i * 4;
        float4 v;
        if (k < kH)
            v = *reinterpret_cast<const float4*>(&g_h[0][0][b * kH + k]);
        else
            v = *reinterpret_cast<const float4*>(&g_h[0][1][b * kH + k - kH]);
        *reinterpret_cast<float4*>(&hc[k]) = v;
    }
    __syncthreads();
    int o = blockIdx.x * 8 + wid;
    const float4* wr = reinterpret_cast<const float4*>(&fcW[(size_t)o * 2 * kH]);
    const float4* hr = reinterpret_cast<const float4*>(hc);
    float sum = 0.0f;
    for (int i = lane; i < (2 * kH) / 4; i += 32) {
        float4 w = wr[i], h = hr[i];
        sum += w.x * h.x + w.y * h.y + w.z * h.z + w.w * h.w;
    }
#pragma unroll
    for (int off = 16; off; off >>= 1)
        sum += __shfl_xor_sync(0xffffffff, sum, off);
    if (lane == 0) out[kOUTSZ + (size_t)b * kH + o] = tanhf(sum + fcb[o]);
}

// ---------------------------------------------------------------------------
extern "C" void kernel_launch(void* const* d_in, const int* in_sizes, int n_in,
                              void* d_out, int out_size) {
    const int* seqs      = (const int*)d_in[0];
    const float* embW    = (const float*)d_in[1];
    const float* W_ih_f  = (const float*)d_in[2];
    const float* W_hh_f  = (const float*)d_in[3];
    const float* b_ih_f  = (const float*)d_in[4];
    const float* b_hh_f  = (const float*)d_in[5];
    const float* W_ih_b  = (const float*)d_in[6];
    const float* W_hh_b  = (const float*)d_in[7];
    const float* b_ih_b  = (const float*)d_in[8];
    const float* b_hh_b  = (const float*)d_in[9];
    const float* fc_W    = (const float*)d_in[10];
    const float* fc_b    = (const float*)d_in[11];
    float* out = (float*)d_out;

    static bool attr_set = false;
    if (!attr_set) {
        cudaFuncSetAttribute(step_persist_kernel,
                             cudaFuncAttributeMaxDynamicSharedMemorySize,
                             (int)SM_BYTES);
        attr_set = true;
    }

    zero_h_kernel<<<1024, 256>>>();
    gather_kernel<<<kBT, 128>>>(seqs, embW);
    xp_gemm_kernel<<<dim3(48, 256, 2), 256>>>(W_ih_f, W_ih_b, b_ih_f, b_ih_b);
    step_persist_kernel<<<128, 384, SM_BYTES>>>(W_hh_f, W_hh_b, b_hh_f, b_hh_b,
                                                out);
    fc_kernel<<<dim3(kH / 8, kB), 256>>>(fc_W, fc_b, out);
}

// round 5
// speedup vs baseline: 1.4011x; 1.4011x over previous
#include <cuda_runtime.h>
#include <cstdint>
#include <mma.h>
using namespace nvcuda;

// Problem dims
constexpr int kB = 64;      // batch
constexpr int kT = 512;     // seq len
constexpr int kE = 512;     // embed
constexpr int kH = 1024;    // hidden
constexpr int kBT = kB * kT;           // 32768
constexpr int k3H = 3 * kH;            // 3072
constexpr size_t kXPSZ = (size_t)kBT * k3H;       // per-dir xp elements
constexpr size_t kOUTSZ = (size_t)kBT * 2 * kH;   // outputs elements

// Scratch
__device__ float g_emb[(size_t)kBT * kE];   // 64 MB
__device__ float g_xp[2 * kXPSZ];           // 805 MB, [dir][t][b][3H]
__device__ float g_h[2][2][kB * kH];        // [parity][dir][B*H] (tf32-rounded)
__device__ unsigned int g_bar[2];           // per-dir step barrier counters

#define CP_ASYNC16(dst, src) \
    asm volatile("cp.async.cg.shared.global [%0], [%1], 16;" ::"r"(dst), "l"(src))
#define CP_COMMIT() asm volatile("cp.async.commit_group;")
#define CP_WAIT1() asm volatile("cp.async.wait_group 1;")

// ---------------------------------------------------------------------------
__global__ void zero_h_kernel() {
    int idx = blockIdx.x * blockDim.x + threadIdx.x;  // 262144 total
    ((float*)g_h)[idx] = 0.0f;
    if (blockIdx.x == 0 && threadIdx.x < 2) g_bar[threadIdx.x] = 0u;
}

// emb[m, :] = embed_W[seqs[m], :]
__global__ void gather_kernel(const int* __restrict__ seqs,
                              const float* __restrict__ embW) {
    int m = blockIdx.x;
    int t4 = threadIdx.x;
    int row = seqs[m];
    reinterpret_cast<float4*>(g_emb)[(size_t)m * (kE / 4) + t4] =
        reinterpret_cast<const float4*>(embW)[(size_t)row * (kE / 4) + t4];
}

// ---------------------------------------------------------------------------
// xp = emb @ W_ih^T + b_ih, output rows remapped to [t][b] order.
__global__ void xp_gemm_kernel(const float* __restrict__ Wf,
                               const float* __restrict__ Wb,
                               const float* __restrict__ bf,
                               const float* __restrict__ bb) {
    constexpr int BM = 128, BN = 64, BK = 16, BKP = 20;
    __shared__ float As[BM][BKP];
    __shared__ float Bs[BN][BKP];
    __shared__ float Cs[8][32][32];

    int dir = blockIdx.z;
    const float* W = dir ? Wb : Wf;
    const float* bias = dir ? bb : bf;
    float* xp = g_xp + (size_t)dir * kXPSZ;

    int m0 = blockIdx.y * BM, n0 = blockIdx.x * BN;
    int tid = threadIdx.x, wid = tid >> 5, lane = tid & 31;
    int wm = wid >> 1, wn = wid & 1;

    wmma::fragment<wmma::accumulator, 16, 16, 8, float> acc[2][2];
#pragma unroll
    for (int i = 0; i < 2; i++)
#pragma unroll
        for (int j = 0; j < 2; j++) wmma::fill_fragment(acc[i][j], 0.0f);

    for (int k0 = 0; k0 < kE; k0 += BK) {
#pragma unroll
        for (int it = 0; it < 2; it++) {
            int i = tid + it * 256;
            int r = i >> 2, c4 = i & 3;
            float4 v = *reinterpret_cast<const float4*>(
                &g_emb[(size_t)(m0 + r) * kE + k0 + c4 * 4]);
            *reinterpret_cast<float4*>(&As[r][c4 * 4]) = v;
        }
        {
            int r = tid >> 2, c4 = tid & 3;
            float4 v = *reinterpret_cast<const float4*>(
                &W[(size_t)(n0 + r) * kE + k0 + c4 * 4]);
            *reinterpret_cast<float4*>(&Bs[r][c4 * 4]) = v;
        }
        __syncthreads();
#pragma unroll
        for (int kk = 0; kk < BK; kk += 8) {
            wmma::fragment<wmma::matrix_a, 16, 16, 8, wmma::precision::tf32,
                           wmma::row_major> a[2];
            wmma::fragment<wmma::matrix_b, 16, 16, 8, wmma::precision::tf32,
                           wmma::col_major> b[2];
            wmma::load_matrix_sync(a[0], &As[wm * 32][kk], BKP);
            wmma::load_matrix_sync(a[1], &As[wm * 32 + 16][kk], BKP);
            wmma::load_matrix_sync(b[0], &Bs[wn * 32][kk], BKP);
            wmma::load_matrix_sync(b[1], &Bs[wn * 32 + 16][kk], BKP);
#pragma unroll
            for (int i = 0; i < 2; i++) {
#pragma unroll
                for (int e = 0; e < a[i].num_elements; e++)
                    a[i].x[e] = wmma::__float_to_tf32(a[i].x[e]);
#pragma unroll
                for (int e = 0; e < b[i].num_elements; e++)
                    b[i].x[e] = wmma::__float_to_tf32(b[i].x[e]);
            }
#pragma unroll
            for (int i = 0; i < 2; i++)
#pragma unroll
                for (int j = 0; j < 2; j++)
                    wmma::mma_sync(acc[i][j], a[i], b[j], acc[i][j]);
        }
        __syncthreads();
    }
#pragma unroll
    for (int i = 0; i < 2; i++)
#pragma unroll
        for (int j = 0; j < 2; j++)
            wmma::store_matrix_sync(&Cs[wid][i * 16][j * 16], acc[i][j], 32,
                                    wmma::mem_row_major);
    __syncwarp();
    int gm = m0 + wm * 32, gn = n0 + wn * 32;
    float bv = bias[gn + lane];
#pragma unroll
    for (int r = 0; r < 32; r++) {
        int m = gm + r;                       // m = b*T + t
        int trow = (m & (kT - 1)) * kB + (m >> 9);  // -> t*B + b
        xp[(size_t)trow * k3H + gn + lane] = Cs[wid][r][lane] + bv;
    }
}

// ---------------------------------------------------------------------------
// Persistent GRU recurrence. 128 blocks (64/dir), 16 hidden cols each.
// W slice resident in SMEM; hprev streamed via 3-stage cp.async pipeline.
constexpr int WS_ST = 1036;                   // 1024 + 12 pad
constexpr int AS_ST = 36;                     // 32 + 4 pad
constexpr int CS_ST = 52;
constexpr int SM_WS = 48 * WS_ST;             // 49728 floats
constexpr int AS_STAGE = kB * AS_ST;          // 2304 floats per stage
constexpr int SM_AS = 3 * AS_STAGE;           // 6912 floats (Cs aliases here)
constexpr int SM_TOTAL_FLOATS = SM_WS + SM_AS + 64;
constexpr size_t SM_BYTES = (size_t)SM_TOTAL_FLOATS * 4;  // 226816 B

__global__ void __launch_bounds__(384, 1)
step_persist_kernel(const float* __restrict__ Whf,
                    const float* __restrict__ Whb,
                    const float* __restrict__ bhf,
                    const float* __restrict__ bhb,
                    float* __restrict__ out) {
    extern __shared__ float sm[];
    float* Ws = sm;                        // [48][WS_ST] tf32-rounded W slice
    float* Asf = sm + SM_WS;               // 3 stages of [64][AS_ST]
    float* Csf = Asf;                      // aliased: [64][CS_ST] after mma
    float* bsl = sm + SM_WS + SM_AS;       // [48]

    int bx = blockIdx.x;
    int dir = bx >> 6;
    int j0 = (bx & 63) * 16;
    const float* W = dir ? Whb : Whf;
    const float* bhh = dir ? bhb : bhf;
    const float* xp = g_xp + (size_t)dir * kXPSZ;

    int tid = threadIdx.x, wid = tid >> 5;
    int g = wid >> 2;      // gate 0..2
    int mt = wid & 3;      // m-tile 0..3
    unsigned int as_smem = (unsigned int)__cvta_generic_to_shared(Asf);

    // preload W slice (48 x 1024), rounded to tf32
    for (int i = tid; i < 48 * 256; i += 384) {
        int r = i >> 8, c4 = i & 255;
        int wrow = (r >> 4) * kH + j0 + (r & 15);
        float4 v = *reinterpret_cast<const float4*>(
            &W[(size_t)wrow * kH + c4 * 4]);
        v.x = wmma::__float_to_tf32(v.x);
        v.y = wmma::__float_to_tf32(v.y);
        v.z = wmma::__float_to_tf32(v.z);
        v.w = wmma::__float_to_tf32(v.w);
        *reinterpret_cast<float4*>(&Ws[r * WS_ST + c4 * 4]) = v;
    }
    if (tid < 48) bsl[tid] = bhh[(tid >> 4) * kH + j0 + (tid & 15)];
    __syncthreads();

    for (int s = 0; s < kT; s++) {
        int parity = s & 1;
        const float* hprev = g_h[parity][dir];
        float* hnext = g_h[parity ^ 1][dir];
        int t_idx = dir ? (kT - 1 - s) : s;

        wmma::fragment<wmma::accumulator, 16, 16, 8, float> acc0, acc1;
        wmma::fill_fragment(acc0, 0.0f);
        wmma::fill_fragment(acc1, 0.0f);

        // issue a K-chunk copy into pipeline slot (chunk % 3)
        auto issue_chunk = [&](int chunk) {
            int slot = chunk % 3;
            for (int i = tid; i < 512; i += 384) {
                int r = i >> 3, c4 = i & 7;
                unsigned int dst =
                    as_smem +
                    (unsigned int)(slot * AS_STAGE + r * AS_ST + c4 * 4) * 4u;
                CP_ASYNC16(dst, hprev + (size_t)r * kH + chunk * 32 + c4 * 4);
            }
        };
        issue_chunk(0); CP_COMMIT();
        issue_chunk(1); CP_COMMIT();

        for (int kc = 0; kc < 32; kc++) {
            CP_WAIT1();          // chunk kc landed
            __syncthreads();     // visible to all warps; prior stage free
            if (kc + 2 < 32) issue_chunk(kc + 2);
            CP_COMMIT();         // always commit (empty ok) to keep count
            const float* abuf = Asf + (kc % 3) * AS_STAGE;
#pragma unroll
            for (int kk = 0; kk < 4; kk++) {
                wmma::fragment<wmma::matrix_a, 16, 16, 8,
                               wmma::precision::tf32, wmma::row_major> a;
                wmma::fragment<wmma::matrix_b, 16, 16, 8,
                               wmma::precision::tf32, wmma::col_major> b;
                wmma::load_matrix_sync(a, &abuf[(mt * 16) * AS_ST + kk * 8],
                                       AS_ST);
                wmma::load_matrix_sync(
                    b, &Ws[(g * 16) * WS_ST + kc * 32 + kk * 8], WS_ST);
                if (kk & 1) wmma::mma_sync(acc1, a, b, acc1);
                else        wmma::mma_sync(acc0, a, b, acc0);
            }
        }
#pragma unroll
        for (int e = 0; e < acc0.num_elements; e++) acc0.x[e] += acc1.x[e];
        __syncthreads();  // all mma reads done; As region reusable as Cs
        wmma::store_matrix_sync(&Csf[(mt * 16) * CS_ST + g * 16], acc0, CS_ST,
                                wmma::mem_row_major);
        __syncthreads();

        // gate fusion + h update + output write
        const float* xpt = xp + (size_t)t_idx * kB * k3H;
        for (int idx = tid; idx < kB * 16; idx += 384) {
            int b = idx >> 4, jj = idx & 15, j = j0 + jj;
            const float* xpr = xpt + (size_t)b * k3H;
            float xr = xpr[j], xz = xpr[kH + j], xn = xpr[2 * kH + j];
            float ghr = Csf[b * CS_ST + jj] + bsl[jj];
            float ghz = Csf[b * CS_ST + 16 + jj] + bsl[16 + jj];
            float ghn = Csf[b * CS_ST + 32 + jj] + bsl[32 + jj];
            float r = 1.0f / (1.0f + __expf(-(xr + ghr)));
            float z = 1.0f / (1.0f + __expf(-(xz + ghz)));
            float n = tanhf(xn + r * ghn);
            float hp = hprev[b * kH + j];
            float hv = (1.0f - z) * n + z * hp;
            hnext[b * kH + j] = wmma::__float_to_tf32(hv);  // pre-rounded
            out[(size_t)(b * kT + t_idx) * (2 * kH) + dir * kH + j] = hv;
        }

        // per-direction global barrier (monotone counter; acquire-load poll)
        __threadfence();
        __syncthreads();
        if (tid == 0) {
            atomicAdd(&g_bar[dir], 1u);
            unsigned int target = 64u * (unsigned int)(s + 1);
            unsigned int v;
            do {
                asm volatile("ld.acquire.gpu.u32 %0, [%1];"
                             : "=r"(v) : "l"(&g_bar[dir]) : "memory");
            } while (v < target);
        }
        __syncthreads();
    }
}

// ---------------------------------------------------------------------------
__global__ void fc_kernel(const float* __restrict__ fcW,
                          const float* __restrict__ fcb,
                          float* __restrict__ out) {
    __shared__ float hc[2 * kH];
    int b = blockIdx.y;
    int tid = threadIdx.x, wid = tid >> 5, lane = tid & 31;
    for (int i = tid; i < (2 * kH) / 4; i += 256) {
        int k = i * 4;
        float4 v;
        if (k < kH)
            v = *reinterpret_cast<const float4*>(&g_h[0][0][b * kH + k]);
        else
            v = *reinterpret_cast<const float4*>(&g_h[0][1][b * kH + k - kH]);
        *reinterpret_cast<float4*>(&hc[k]) = v;
    }
    __syncthreads();
    int o = blockIdx.x * 8 + wid;
    const float4* wr = reinterpret_cast<const float4*>(&fcW[(size_t)o * 2 * kH]);
    const float4* hr = reinterpret_cast<const float4*>(hc);
    float sum = 0.0f;
    for (int i = lane; i < (2 * kH) / 4; i += 32) {
        float4 w = wr[i], h = hr[i];
        sum += w.x * h.x + w.y * h.y + w.z * h.z + w.w * h.w;
    }
#pragma unroll
    for (int off = 16; off; off >>= 1)
        sum += __shfl_xor_sync(0xffffffff, sum, off);
    if (lane == 0) out[kOUTSZ + (size_t)b * kH + o] = tanhf(sum + fcb[o]);
}

// ---------------------------------------------------------------------------
extern "C" void kernel_launch(void* const* d_in, const int* in_sizes, int n_in,
                              void* d_out, int out_size) {
    const int* seqs      = (const int*)d_in[0];
    const float* embW    = (const float*)d_in[1];
    const float* W_ih_f  = (const float*)d_in[2];
    const float* W_hh_f  = (const float*)d_in[3];
    const float* b_ih_f  = (const float*)d_in[4];
    const float* b_hh_f  = (const float*)d_in[5];
    const float* W_ih_b  = (const float*)d_in[6];
    const float* W_hh_b  = (const float*)d_in[7];
    const float* b_ih_b  = (const float*)d_in[8];
    const float* b_hh_b  = (const float*)d_in[9];
    const float* fc_W    = (const float*)d_in[10];
    const float* fc_b    = (const float*)d_in[11];
    float* out = (float*)d_out;

    static bool attr_set = false;
    if (!attr_set) {
        cudaFuncSetAttribute(step_persist_kernel,
                             cudaFuncAttributeMaxDynamicSharedMemorySize,
                             (int)SM_BYTES);
        attr_set = true;
    }

    zero_h_kernel<<<1024, 256>>>();
    gather_kernel<<<kBT, 128>>>(seqs, embW);
    xp_gemm_kernel<<<dim3(48, 256, 2), 256>>>(W_ih_f, W_ih_b, b_ih_f, b_ih_b);
    step_persist_kernel<<<128, 384, SM_BYTES>>>(W_hh_f, W_hh_b, b_hh_f, b_hh_b,
                                                out);
    fc_kernel<<<dim3(kH / 8, kB), 256>>>(fc_W, fc_b, out);
}

// round 6
// speedup vs baseline: 1.5826x; 1.1296x over previous
#include <cuda_runtime.h>
#include <cstdint>
#include <mma.h>
using namespace nvcuda;

// Problem dims
constexpr int kB = 64;      // batch
constexpr int kT = 512;     // seq len
constexpr int kE = 512;     // embed
constexpr int kH = 1024;    // hidden
constexpr int kBT = kB * kT;           // 32768
constexpr int k3H = 3 * kH;            // 3072
constexpr size_t kXPSZ = (size_t)kBT * k3H;       // per-dir xp elements
constexpr size_t kOUTSZ = (size_t)kBT * 2 * kH;   // outputs elements

// Scratch
__device__ float g_emb[(size_t)kBT * kE];   // 64 MB
__device__ float g_xp[2 * kXPSZ];           // 805 MB, [dir][t][b][3H]
__device__ float g_h[2][2][kB * kH];        // [parity][dir][B*H] (tf32-rounded)
__device__ unsigned int g_bar[2];           // per-dir step barrier counters

#define CP_ASYNC16(dst, src) \
    asm volatile("cp.async.cg.shared.global [%0], [%1], 16;" ::"r"(dst), "l"(src))
#define CP_COMMIT() asm volatile("cp.async.commit_group;")
#define CP_WAIT2() asm volatile("cp.async.wait_group 2;")
#define CP_WAIT0() asm volatile("cp.async.wait_group 0;")
#define BAR_SYNC(id, cnt) \
    asm volatile("bar.sync %0, %1;" ::"r"(id), "r"(cnt) : "memory")
#define BAR_ARRIVE(id, cnt) \
    asm volatile("bar.arrive %0, %1;" ::"r"(id), "r"(cnt) : "memory")

// ---------------------------------------------------------------------------
__global__ void zero_h_kernel() {
    int idx = blockIdx.x * blockDim.x + threadIdx.x;  // 262144 total
    ((float*)g_h)[idx] = 0.0f;
    if (blockIdx.x == 0 && threadIdx.x < 2) g_bar[threadIdx.x] = 0u;
}

__global__ void gather_kernel(const int* __restrict__ seqs,
                              const float* __restrict__ embW) {
    int m = blockIdx.x;
    int t4 = threadIdx.x;
    int row = seqs[m];
    reinterpret_cast<float4*>(g_emb)[(size_t)m * (kE / 4) + t4] =
        reinterpret_cast<const float4*>(embW)[(size_t)row * (kE / 4) + t4];
}

// ---------------------------------------------------------------------------
// xp = emb @ W_ih^T + b_ih, output rows remapped to [t][b] order.
__global__ void xp_gemm_kernel(const float* __restrict__ Wf,
                               const float* __restrict__ Wb,
                               const float* __restrict__ bf,
                               const float* __restrict__ bb) {
    constexpr int BM = 128, BN = 64, BK = 16, BKP = 20;
    __shared__ float As[BM][BKP];
    __shared__ float Bs[BN][BKP];
    __shared__ float Cs[8][32][32];

    int dir = blockIdx.z;
    const float* W = dir ? Wb : Wf;
    const float* bias = dir ? bb : bf;
    float* xp = g_xp + (size_t)dir * kXPSZ;

    int m0 = blockIdx.y * BM, n0 = blockIdx.x * BN;
    int tid = threadIdx.x, wid = tid >> 5, lane = tid & 31;
    int wm = wid >> 1, wn = wid & 1;

    wmma::fragment<wmma::accumulator, 16, 16, 8, float> acc[2][2];
#pragma unroll
    for (int i = 0; i < 2; i++)
#pragma unroll
        for (int j = 0; j < 2; j++) wmma::fill_fragment(acc[i][j], 0.0f);

    for (int k0 = 0; k0 < kE; k0 += BK) {
#pragma unroll
        for (int it = 0; it < 2; it++) {
            int i = tid + it * 256;
            int r = i >> 2, c4 = i & 3;
            float4 v = *reinterpret_cast<const float4*>(
                &g_emb[(size_t)(m0 + r) * kE + k0 + c4 * 4]);
            *reinterpret_cast<float4*>(&As[r][c4 * 4]) = v;
        }
        {
            int r = tid >> 2, c4 = tid & 3;
            float4 v = *reinterpret_cast<const float4*>(
                &W[(size_t)(n0 + r) * kE + k0 + c4 * 4]);
            *reinterpret_cast<float4*>(&Bs[r][c4 * 4]) = v;
        }
        __syncthreads();
#pragma unroll
        for (int kk = 0; kk < BK; kk += 8) {
            wmma::fragment<wmma::matrix_a, 16, 16, 8, wmma::precision::tf32,
                           wmma::row_major> a[2];
            wmma::fragment<wmma::matrix_b, 16, 16, 8, wmma::precision::tf32,
                           wmma::col_major> b[2];
            wmma::load_matrix_sync(a[0], &As[wm * 32][kk], BKP);
            wmma::load_matrix_sync(a[1], &As[wm * 32 + 16][kk], BKP);
            wmma::load_matrix_sync(b[0], &Bs[wn * 32][kk], BKP);
            wmma::load_matrix_sync(b[1], &Bs[wn * 32 + 16][kk], BKP);
#pragma unroll
            for (int i = 0; i < 2; i++) {
#pragma unroll
                for (int e = 0; e < a[i].num_elements; e++)
                    a[i].x[e] = wmma::__float_to_tf32(a[i].x[e]);
#pragma unroll
                for (int e = 0; e < b[i].num_elements; e++)
                    b[i].x[e] = wmma::__float_to_tf32(b[i].x[e]);
            }
#pragma unroll
            for (int i = 0; i < 2; i++)
#pragma unroll
                for (int j = 0; j < 2; j++)
                    wmma::mma_sync(acc[i][j], a[i], b[j], acc[i][j]);
        }
        __syncthreads();
    }
#pragma unroll
    for (int i = 0; i < 2; i++)
#pragma unroll
        for (int j = 0; j < 2; j++)
            wmma::store_matrix_sync(&Cs[wid][i * 16][j * 16], acc[i][j], 32,
                                    wmma::mem_row_major);
    __syncwarp();
    int gm = m0 + wm * 32, gn = n0 + wn * 32;
    float bv = bias[gn + lane];
#pragma unroll
    for (int r = 0; r < 32; r++) {
        int m = gm + r;                       // m = b*T + t
        int trow = (m & (kT - 1)) * kB + (m >> 9);  // -> t*B + b
        xp[(size_t)trow * k3H + gn + lane] = Cs[wid][r][lane] + bv;
    }
}

// ---------------------------------------------------------------------------
// Persistent GRU recurrence, warp-specialized. 128 blocks (64/dir), 16 cols.
// 13 warps: 12 consumers (4 m-tiles x 3 gates) + 1 producer (cp.async).
// Named barriers: FULL[slot]=1+slot, EMPTY[slot]=4+slot, count=416.
constexpr int WS_ST = 1028;                   // 1024 + 4 pad (banks 4g+c: ok)
constexpr int AS_ST = 36;                     // 32 + 4 pad
constexpr int CS_ST = 52;
constexpr int SM_WS = 48 * WS_ST;             // 49344 floats
constexpr int AS_STAGE = kB * AS_ST;          // 2304 floats per stage
constexpr int SM_AS = 3 * AS_STAGE;           // 6912 floats (Cs aliases here)
constexpr int SM_TOTAL_FLOATS = SM_WS + SM_AS + 64;
constexpr size_t SM_BYTES = (size_t)SM_TOTAL_FLOATS * 4;  // 225280 B
constexpr int NTHR = 416;                     // 13 warps

__global__ void __launch_bounds__(NTHR, 1)
step_persist_kernel(const float* __restrict__ Whf,
                    const float* __restrict__ Whb,
                    const float* __restrict__ bhf,
                    const float* __restrict__ bhb,
                    float* __restrict__ out) {
    extern __shared__ float sm[];
    float* Ws = sm;                        // [48][WS_ST] tf32-rounded W slice
    float* Asf = sm + SM_WS;               // 3 stages of [64][AS_ST]
    float* Csf = Asf;                      // aliased: [64][CS_ST] after mma
    float* bsl = sm + SM_WS + SM_AS;       // [48]

    int bx = blockIdx.x;
    int dir = bx >> 6;
    int j0 = (bx & 63) * 16;
    const float* W = dir ? Whb : Whf;
    const float* bhh = dir ? bhb : bhf;
    const float* xp = g_xp + (size_t)dir * kXPSZ;

    int tid = threadIdx.x, wid = tid >> 5, lane = tid & 31;
    int g = wid >> 2;      // consumer: gate 0..2
    int mt = wid & 3;      // consumer: m-tile 0..3
    bool is_producer = (wid == 12);
    unsigned int as_smem = (unsigned int)__cvta_generic_to_shared(Asf);

    // preload W slice (48 x 1024), rounded to tf32
    for (int i = tid; i < 48 * 256; i += NTHR) {
        int r = i >> 8, c4 = i & 255;
        int wrow = (r >> 4) * kH + j0 + (r & 15);
        float4 v = *reinterpret_cast<const float4*>(
            &W[(size_t)wrow * kH + c4 * 4]);
        v.x = wmma::__float_to_tf32(v.x);
        v.y = wmma::__float_to_tf32(v.y);
        v.z = wmma::__float_to_tf32(v.z);
        v.w = wmma::__float_to_tf32(v.w);
        *reinterpret_cast<float4*>(&Ws[r * WS_ST + c4 * 4]) = v;
    }
    if (tid < 48) bsl[tid] = bhh[(tid >> 4) * kH + j0 + (tid & 15)];
    __syncthreads();

    // consumers pre-arrive all EMPTY barriers once (producer gets 1-use lead)
    if (!is_producer) {
        BAR_ARRIVE(4, NTHR);
        BAR_ARRIVE(5, NTHR);
        BAR_ARRIVE(6, NTHR);
    }

    for (int s = 0; s < kT; s++) {
        int parity = s & 1;
        const float* hprev = g_h[parity][dir];
        float* hnext = g_h[parity ^ 1][dir];
        int t_idx = dir ? (kT - 1 - s) : s;
        const float* xpt = xp + (size_t)t_idx * kB * k3H;

        // preload epilogue operands into regs (latency hides behind K loop)
        float pxr[3], pxz[3], pxn[3], php[3];
#pragma unroll
        for (int k = 0; k < 3; k++) {
            int idx = tid + k * NTHR;
            if (idx < kB * 16) {
                int b = idx >> 4, jj = idx & 15, j = j0 + jj;
                const float* xpr = xpt + (size_t)b * k3H;
                pxr[k] = xpr[j];
                pxz[k] = xpr[kH + j];
                pxn[k] = xpr[2 * kH + j];
                php[k] = hprev[b * kH + j];
            }
        }

        if (!is_producer) {
            // ---------------- consumers: 32 chunks of K=32 ----------------
            wmma::fragment<wmma::accumulator, 16, 16, 8, float> acc0, acc1;
            wmma::fill_fragment(acc0, 0.0f);
            wmma::fill_fragment(acc1, 0.0f);
            const float* wsg = &Ws[(g * 16) * WS_ST];
#pragma unroll 1
            for (int c = 0; c < 32; c++) {
                int slot = c % 3;
                // B fragments: resident W, load BEFORE the FULL wait
                wmma::fragment<wmma::matrix_b, 16, 16, 8,
                               wmma::precision::tf32, wmma::col_major> bfr[4];
#pragma unroll
                for (int kk = 0; kk < 4; kk++)
                    wmma::load_matrix_sync(bfr[kk], &wsg[c * 32 + kk * 8],
                                           WS_ST);
                BAR_SYNC(1 + slot, NTHR);
                const float* abuf =
                    Asf + slot * AS_STAGE + (mt * 16) * AS_ST;
#pragma unroll
                for (int kk = 0; kk < 4; kk++) {
                    wmma::fragment<wmma::matrix_a, 16, 16, 8,
                                   wmma::precision::tf32, wmma::row_major> a;
                    wmma::load_matrix_sync(a, &abuf[kk * 8], AS_ST);
                    if (kk & 1) wmma::mma_sync(acc1, a, bfr[kk], acc1);
                    else        wmma::mma_sync(acc0, a, bfr[kk], acc0);
                }
                BAR_ARRIVE(4 + slot, NTHR);
            }
#pragma unroll
            for (int e = 0; e < acc0.num_elements; e++) acc0.x[e] += acc1.x[e];
            __syncthreads();  // join producer; stages now reusable as Cs
            wmma::store_matrix_sync(&Csf[(mt * 16) * CS_ST + g * 16], acc0,
                                    CS_ST, wmma::mem_row_major);
        } else {
            // ---------------- producer: fill stages, signal FULL ----------
#pragma unroll 1
            for (int c = 0; c < 32; c++) {
                int slot = c % 3;
                BAR_SYNC(4 + slot, NTHR);  // stage free?
                const float* src = hprev + c * 32;
                unsigned int dstb = as_smem + (unsigned int)(slot * AS_STAGE) * 4u;
#pragma unroll
                for (int it = 0; it < 16; it++) {
                    int i = lane + it * 32;
                    int r = i >> 3, c4 = i & 7;
                    CP_ASYNC16(dstb + (unsigned int)(r * AS_ST + c4 * 4) * 4u,
                               src + (size_t)r * kH + c4 * 4);
                }
                CP_COMMIT();
                if (c >= 2) {
                    CP_WAIT2();
                    BAR_ARRIVE(1 + ((c - 2) % 3), NTHR);
                }
            }
            CP_WAIT0();
            BAR_ARRIVE(1 + 0, NTHR);  // chunk 30 -> slot 0
            BAR_ARRIVE(1 + 1, NTHR);  // chunk 31 -> slot 1
            __syncthreads();
        }
        __syncthreads();  // Cs visible to all

        // gate fusion + h update + output write (all 416 threads)
#pragma unroll
        for (int k = 0; k < 3; k++) {
            int idx = tid + k * NTHR;
            if (idx < kB * 16) {
                int b = idx >> 4, jj = idx & 15, j = j0 + jj;
                float ghr = Csf[b * CS_ST + jj] + bsl[jj];
                float ghz = Csf[b * CS_ST + 16 + jj] + bsl[16 + jj];
                float ghn = Csf[b * CS_ST + 32 + jj] + bsl[32 + jj];
                float r = 1.0f / (1.0f + __expf(-(pxr[k] + ghr)));
                float z = 1.0f / (1.0f + __expf(-(pxz[k] + ghz)));
                float n = tanhf(pxn[k] + r * ghn);
                float hv = (1.0f - z) * n + z * php[k];
                hnext[b * kH + j] = wmma::__float_to_tf32(hv);
                out[(size_t)(b * kT + t_idx) * (2 * kH) + dir * kH + j] = hv;
            }
        }

        // per-direction global barrier
        __threadfence();
        __syncthreads();
        if (tid == 0) {
            atomicAdd(&g_bar[dir], 1u);
            unsigned int target = 64u * (unsigned int)(s + 1);
            unsigned int v;
            do {
                asm volatile("ld.acquire.gpu.u32 %0, [%1];"
                             : "=r"(v) : "l"(&g_bar[dir]) : "memory");
            } while (v < target);
        }
        __syncthreads();
    }
}

// ---------------------------------------------------------------------------
__global__ void fc_kernel(const float* __restrict__ fcW,
                          const float* __restrict__ fcb,
                          float* __restrict__ out) {
    __shared__ float hc[2 * kH];
    int b = blockIdx.y;
    int tid = threadIdx.x, wid = tid >> 5, lane = tid & 31;
    for (int i = tid; i < (2 * kH) / 4; i += 256) {
        int k = i * 4;
        float4 v;
        if (k < kH)
            v = *reinterpret_cast<const float4*>(&g_h[0][0][b * kH + k]);
        else
            v = *reinterpret_cast<const float4*>(&g_h[0][1][b * kH + k - kH]);
        *reinterpret_cast<float4*>(&hc[k]) = v;
    }
    __syncthreads();
    int o = blockIdx.x * 8 + wid;
    const float4* wr = reinterpret_cast<const float4*>(&fcW[(size_t)o * 2 * kH]);
    const float4* hr = reinterpret_cast<const float4*>(hc);
    float sum = 0.0f;
    for (int i = lane; i < (2 * kH) / 4; i += 32) {
        float4 w = wr[i], h = hr[i];
        sum += w.x * h.x + w.y * h.y + w.z * h.z + w.w * h.w;
    }
#pragma unroll
    for (int off = 16; off; off >>= 1)
        sum += __shfl_xor_sync(0xffffffff, sum, off);
    if (lane == 0) out[kOUTSZ + (size_t)b * kH + o] = tanhf(sum + fcb[o]);
}

// ---------------------------------------------------------------------------
extern "C" void kernel_launch(void* const* d_in, const int* in_sizes, int n_in,
                              void* d_out, int out_size) {
    const int* seqs      = (const int*)d_in[0];
    const float* embW    = (const float*)d_in[1];
    const float* W_ih_f  = (const float*)d_in[2];
    const float* W_hh_f  = (const float*)d_in[3];
    const float* b_ih_f  = (const float*)d_in[4];
    const float* b_hh_f  = (const float*)d_in[5];
    const float* W_ih_b  = (const float*)d_in[6];
    const float* W_hh_b  = (const float*)d_in[7];
    const float* b_ih_b  = (const float*)d_in[8];
    const float* b_hh_b  = (const float*)d_in[9];
    const float* fc_W    = (const float*)d_in[10];
    const float* fc_b    = (const float*)d_in[11];
    float* out = (float*)d_out;

    static bool attr_set = false;
    if (!attr_set) {
        cudaFuncSetAttribute(step_persist_kernel,
                             cudaFuncAttributeMaxDynamicSharedMemorySize,
                             (int)SM_BYTES);
        attr_set = true;
    }

    zero_h_kernel<<<1024, 256>>>();
    gather_kernel<<<kBT, 128>>>(seqs, embW);
    xp_gemm_kernel<<<dim3(48, 256, 2), 256>>>(W_ih_f, W_ih_b, b_ih_f, b_ih_b);
    step_persist_kernel<<<128, NTHR, SM_BYTES>>>(W_hh_f, W_hh_b, b_hh_f,
                                                 b_hh_b, out);
    fc_kernel<<<dim3(kH / 8, kB), 256>>>(fc_W, fc_b, out);
}

// round 7
// speedup vs baseline: 1.8395x; 1.1623x over previous
#include <cuda_runtime.h>
#include <cstdint>
#include <mma.h>
using namespace nvcuda;

// Problem dims
constexpr int kB = 64;      // batch
constexpr int kT = 512;     // seq len
constexpr int kE = 512;     // embed
constexpr int kH = 1024;    // hidden
constexpr int kBT = kB * kT;           // 32768
constexpr int k3H = 3 * kH;            // 3072
constexpr size_t kXPSZ = (size_t)kBT * k3H;       // per-dir xp elements
constexpr size_t kOUTSZ = (size_t)kBT * 2 * kH;   // outputs elements

// Scratch
__device__ float g_emb[(size_t)kBT * kE];   // 64 MB
__device__ float g_xp[2 * kXPSZ];           // 805 MB, [dir][t][b][3H]
__device__ float g_h[2][2][kB * kH];        // [parity][dir][B*H] (tf32-rounded)
__device__ unsigned int g_bar[2];           // per-dir step barrier counters

// ---------------------------------------------------------------------------
__global__ void zero_h_kernel() {
    int idx = blockIdx.x * blockDim.x + threadIdx.x;  // 262144 total
    ((float*)g_h)[idx] = 0.0f;
    if (blockIdx.x == 0 && threadIdx.x < 2) g_bar[threadIdx.x] = 0u;
}

__global__ void gather_kernel(const int* __restrict__ seqs,
                              const float* __restrict__ embW) {
    int m = blockIdx.x;
    int t4 = threadIdx.x;
    int row = seqs[m];
    reinterpret_cast<float4*>(g_emb)[(size_t)m * (kE / 4) + t4] =
        reinterpret_cast<const float4*>(embW)[(size_t)row * (kE / 4) + t4];
}

// ---------------------------------------------------------------------------
// xp = emb @ W_ih^T + b_ih, output rows remapped to [t][b] order.
__global__ void xp_gemm_kernel(const float* __restrict__ Wf,
                               const float* __restrict__ Wb,
                               const float* __restrict__ bf,
                               const float* __restrict__ bb) {
    constexpr int BM = 128, BN = 64, BK = 16, BKP = 20;
    __shared__ float As[BM][BKP];
    __shared__ float Bs[BN][BKP];
    __shared__ float Cs[8][32][32];

    int dir = blockIdx.z;
    const float* W = dir ? Wb : Wf;
    const float* bias = dir ? bb : bf;
    float* xp = g_xp + (size_t)dir * kXPSZ;

    int m0 = blockIdx.y * BM, n0 = blockIdx.x * BN;
    int tid = threadIdx.x, wid = tid >> 5, lane = tid & 31;
    int wm = wid >> 1, wn = wid & 1;

    wmma::fragment<wmma::accumulator, 16, 16, 8, float> acc[2][2];
#pragma unroll
    for (int i = 0; i < 2; i++)
#pragma unroll
        for (int j = 0; j < 2; j++) wmma::fill_fragment(acc[i][j], 0.0f);

    for (int k0 = 0; k0 < kE; k0 += BK) {
#pragma unroll
        for (int it = 0; it < 2; it++) {
            int i = tid + it * 256;
            int r = i >> 2, c4 = i & 3;
            float4 v = *reinterpret_cast<const float4*>(
                &g_emb[(size_t)(m0 + r) * kE + k0 + c4 * 4]);
            *reinterpret_cast<float4*>(&As[r][c4 * 4]) = v;
        }
        {
            int r = tid >> 2, c4 = tid & 3;
            float4 v = *reinterpret_cast<const float4*>(
                &W[(size_t)(n0 + r) * kE + k0 + c4 * 4]);
            *reinterpret_cast<float4*>(&Bs[r][c4 * 4]) = v;
        }
        __syncthreads();
#pragma unroll
        for (int kk = 0; kk < BK; kk += 8) {
            wmma::fragment<wmma::matrix_a, 16, 16, 8, wmma::precision::tf32,
                           wmma::row_major> a[2];
            wmma::fragment<wmma::matrix_b, 16, 16, 8, wmma::precision::tf32,
                           wmma::col_major> b[2];
            wmma::load_matrix_sync(a[0], &As[wm * 32][kk], BKP);
            wmma::load_matrix_sync(a[1], &As[wm * 32 + 16][kk], BKP);
            wmma::load_matrix_sync(b[0], &Bs[wn * 32][kk], BKP);
            wmma::load_matrix_sync(b[1], &Bs[wn * 32 + 16][kk], BKP);
#pragma unroll
            for (int i = 0; i < 2; i++) {
#pragma unroll
                for (int e = 0; e < a[i].num_elements; e++)
                    a[i].x[e] = wmma::__float_to_tf32(a[i].x[e]);
#pragma unroll
                for (int e = 0; e < b[i].num_elements; e++)
                    b[i].x[e] = wmma::__float_to_tf32(b[i].x[e]);
            }
#pragma unroll
            for (int i = 0; i < 2; i++)
#pragma unroll
                for (int j = 0; j < 2; j++)
                    wmma::mma_sync(acc[i][j], a[i], b[j], acc[i][j]);
        }
        __syncthreads();
    }
#pragma unroll
    for (int i = 0; i < 2; i++)
#pragma unroll
        for (int j = 0; j < 2; j++)
            wmma::store_matrix_sync(&Cs[wid][i * 16][j * 16], acc[i][j], 32,
                                    wmma::mem_row_major);
    __syncwarp();
    int gm = m0 + wm * 32, gn = n0 + wn * 32;
    float bv = bias[gn + lane];
#pragma unroll
    for (int r = 0; r < 32; r++) {
        int m = gm + r;                       // m = b*T + t
        int trow = (m & (kT - 1)) * kB + (m >> 9);  // -> t*B + b
        xp[(size_t)trow * k3H + gn + lane] = Cs[wid][r][lane] + bv;
    }
}

// ---------------------------------------------------------------------------
// Persistent GRU recurrence, barrier-free mainloop.
// 128 blocks (64/dir), 16 hidden cols each. 16 warps = 4 m-tiles x 4 K-quarters;
// each warp computes 3 gate accumulators over its K-quarter, loading A
// fragments DIRECTLY from global (L2) and B from SMEM-resident W.
// K-partials reduced via 2 SMEM buffers + 2 syncthreads.
constexpr int WS_ST = 1028;                   // 1024 + 4 pad
constexpr int CS_ST = 52;
constexpr int SM_WS = 48 * WS_ST;             // 49344 floats
constexpr int SM_CBUF = kB * CS_ST;           // 3328 floats per buffer
constexpr int SM_TOTAL_FLOATS = SM_WS + 2 * SM_CBUF + 64;
constexpr size_t SM_BYTES = (size_t)SM_TOTAL_FLOATS * 4;  // ~224 KB
constexpr int NTHR = 512;                     // 16 warps

__global__ void __launch_bounds__(NTHR, 1)
step_persist_kernel(const float* __restrict__ Whf,
                    const float* __restrict__ Whb,
                    const float* __restrict__ bhf,
                    const float* __restrict__ bhb,
                    float* __restrict__ out) {
    extern __shared__ float sm[];
    float* Ws = sm;                        // [48][WS_ST] tf32-rounded W slice
    float* bufA = sm + SM_WS;              // [64][CS_ST] partials ks 0+2
    float* bufB = bufA + SM_CBUF;          // [64][CS_ST] partials ks 1+3
    float* bsl = bufB + SM_CBUF;           // [48]

    int bx = blockIdx.x;
    int dir = bx >> 6;
    int j0 = (bx & 63) * 16;
    const float* W = dir ? Whb : Whf;
    const float* bhh = dir ? bhb : bhf;
    const float* xp = g_xp + (size_t)dir * kXPSZ;

    int tid = threadIdx.x, wid = tid >> 5;
    int ks = wid >> 2;     // K-quarter 0..3 (256 K each)
    int mt = wid & 3;      // m-tile 0..3

    // preload W slice (48 x 1024), rounded to tf32
    for (int i = tid; i < 48 * 256; i += NTHR) {
        int r = i >> 8, c4 = i & 255;
        int wrow = (r >> 4) * kH + j0 + (r & 15);
        float4 v = *reinterpret_cast<const float4*>(
            &W[(size_t)wrow * kH + c4 * 4]);
        v.x = wmma::__float_to_tf32(v.x);
        v.y = wmma::__float_to_tf32(v.y);
        v.z = wmma::__float_to_tf32(v.z);
        v.w = wmma::__float_to_tf32(v.w);
        *reinterpret_cast<float4*>(&Ws[r * WS_ST + c4 * 4]) = v;
    }
    if (tid < 48) bsl[tid] = bhh[(tid >> 4) * kH + j0 + (tid & 15)];
    __syncthreads();

    for (int s = 0; s < kT; s++) {
        int parity = s & 1;
        const float* hprev = g_h[parity][dir];
        float* hnext = g_h[parity ^ 1][dir];
        int t_idx = dir ? (kT - 1 - s) : s;
        const float* xpt = xp + (size_t)t_idx * kB * k3H;

        // preload epilogue operands (latency hides behind mainloop)
        float pxr[2], pxz[2], pxn[2], php[2];
#pragma unroll
        for (int k = 0; k < 2; k++) {
            int idx = tid + k * NTHR;  // < 1024 always
            int b = idx >> 4, jj = idx & 15, j = j0 + jj;
            const float* xpr = xpt + (size_t)b * k3H;
            pxr[k] = xpr[j];
            pxz[k] = xpr[kH + j];
            pxn[k] = xpr[2 * kH + j];
            php[k] = hprev[b * kH + j];
        }

        // ---------------- mainloop: no block syncs -----------------------
        // A fragments straight from global (values already tf32-rounded);
        // B fragments from SMEM-resident W (already tf32-rounded).
        wmma::fragment<wmma::accumulator, 16, 16, 8, float> acc[3];
#pragma unroll
        for (int g = 0; g < 3; g++) wmma::fill_fragment(acc[g], 0.0f);

        const float* aBase = hprev + (size_t)(mt * 16) * kH + ks * 256;
        wmma::fragment<wmma::matrix_a, 16, 16, 8, wmma::precision::tf32,
                       wmma::row_major> afr[2];
        wmma::load_matrix_sync(afr[0], aBase, kH);
#pragma unroll 4
        for (int f = 0; f < 32; f++) {
            int cur = f & 1;
            if (f < 31)
                wmma::load_matrix_sync(afr[cur ^ 1], aBase + (f + 1) * 8, kH);
            int kcol = ks * 256 + f * 8;
#pragma unroll
            for (int g = 0; g < 3; g++) {
                wmma::fragment<wmma::matrix_b, 16, 16, 8,
                               wmma::precision::tf32, wmma::col_major> b;
                wmma::load_matrix_sync(b, &Ws[(g * 16) * WS_ST + kcol], WS_ST);
                wmma::mma_sync(acc[g], afr[cur], b, acc[g]);
            }
        }

        // ---------------- K-partial reduction (2 syncs) -------------------
        float* mybuf = (ks & 1) ? bufB : bufA;
        if (ks >= 2) {
#pragma unroll
            for (int g = 0; g < 3; g++)
                wmma::store_matrix_sync(&mybuf[(mt * 16) * CS_ST + g * 16],
                                        acc[g], CS_ST, wmma::mem_row_major);
        }
        __syncthreads();
        if (ks < 2) {
#pragma unroll
            for (int g = 0; g < 3; g++) {
                wmma::fragment<wmma::accumulator, 16, 16, 8, float> c;
                wmma::load_matrix_sync(c, &mybuf[(mt * 16) * CS_ST + g * 16],
                                       CS_ST, wmma::mem_row_major);
#pragma unroll
                for (int e = 0; e < c.num_elements; e++)
                    acc[g].x[e] += c.x[e];
                wmma::store_matrix_sync(&mybuf[(mt * 16) * CS_ST + g * 16],
                                        acc[g], CS_ST, wmma::mem_row_major);
            }
        }
        __syncthreads();

        // ---------------- gate fusion + h update + output -----------------
#pragma unroll
        for (int k = 0; k < 2; k++) {
            int idx = tid + k * NTHR;
            int b = idx >> 4, jj = idx & 15, j = j0 + jj;
            float ghr = bufA[b * CS_ST + jj] + bufB[b * CS_ST + jj] + bsl[jj];
            float ghz = bufA[b * CS_ST + 16 + jj] + bufB[b * CS_ST + 16 + jj] +
                        bsl[16 + jj];
            float ghn = bufA[b * CS_ST + 32 + jj] + bufB[b * CS_ST + 32 + jj] +
                        bsl[32 + jj];
            float r = 1.0f / (1.0f + __expf(-(pxr[k] + ghr)));
            float z = 1.0f / (1.0f + __expf(-(pxz[k] + ghz)));
            float n = tanhf(pxn[k] + r * ghn);
            float hv = (1.0f - z) * n + z * php[k];
            hnext[b * kH + j] = wmma::__float_to_tf32(hv);
            out[(size_t)(b * kT + t_idx) * (2 * kH) + dir * kH + j] = hv;
        }

        // per-direction global barrier (monotone counter; acquire-load poll)
        __threadfence();
        __syncthreads();
        if (tid == 0) {
            atomicAdd(&g_bar[dir], 1u);
            unsigned int target = 64u * (unsigned int)(s + 1);
            unsigned int v;
            do {
                asm volatile("ld.acquire.gpu.u32 %0, [%1];"
                             : "=r"(v) : "l"(&g_bar[dir]) : "memory");
            } while (v < target);
        }
        __syncthreads();
    }
}

// ---------------------------------------------------------------------------
__global__ void fc_kernel(const float* __restrict__ fcW,
                          const float* __restrict__ fcb,
                          float* __restrict__ out) {
    __shared__ float hc[2 * kH];
    int b = blockIdx.y;
    int tid = threadIdx.x, wid = tid >> 5, lane = tid & 31;
    for (int i = tid; i < (2 * kH) / 4; i += 256) {
        int k = i * 4;
        float4 v;
        if (k < kH)
            v = *reinterpret_cast<const float4*>(&g_h[0][0][b * kH + k]);
        else
            v = *reinterpret_cast<const float4*>(&g_h[0][1][b * kH + k - kH]);
        *reinterpret_cast<float4*>(&hc[k]) = v;
    }
    __syncthreads();
    int o = blockIdx.x * 8 + wid;
    const float4* wr = reinterpret_cast<const float4*>(&fcW[(size_t)o * 2 * kH]);
    const float4* hr = reinterpret_cast<const float4*>(hc);
    float sum = 0.0f;
    for (int i = lane; i < (2 * kH) / 4; i += 32) {
        float4 w = wr[i], h = hr[i];
        sum += w.x * h.x + w.y * h.y + w.z * h.z + w.w * h.w;
    }
#pragma unroll
    for (int off = 16; off; off >>= 1)
        sum += __shfl_xor_sync(0xffffffff, sum, off);
    if (lane == 0) out[kOUTSZ + (size_t)b * kH + o] = tanhf(sum + fcb[o]);
}

// ---------------------------------------------------------------------------
extern "C" void kernel_launch(void* const* d_in, const int* in_sizes, int n_in,
                              void* d_out, int out_size) {
    const int* seqs      = (const int*)d_in[0];
    const float* embW    = (const float*)d_in[1];
    const float* W_ih_f  = (const float*)d_in[2];
    const float* W_hh_f  = (const float*)d_in[3];
    const float* b_ih_f  = (const float*)d_in[4];
    const float* b_hh_f  = (const float*)d_in[5];
    const float* W_ih_b  = (const float*)d_in[6];
    const float* W_hh_b  = (const float*)d_in[7];
    const float* b_ih_b  = (const float*)d_in[8];
    const float* b_hh_b  = (const float*)d_in[9];
    const float* fc_W    = (const float*)d_in[10];
    const float* fc_b    = (const float*)d_in[11];
    float* out = (float*)d_out;

    static bool attr_set = false;
    if (!attr_set) {
        cudaFuncSetAttribute(step_persist_kernel,
                             cudaFuncAttributeMaxDynamicSharedMemorySize,
                             (int)SM_BYTES);
        attr_set = true;
    }

    zero_h_kernel<<<1024, 256>>>();
    gather_kernel<<<kBT, 128>>>(seqs, embW);
    xp_gemm_kernel<<<dim3(48, 256, 2), 256>>>(W_ih_f, W_ih_b, b_ih_f, b_ih_b);
    step_persist_kernel<<<128, NTHR, SM_BYTES>>>(W_hh_f, W_hh_b, b_hh_f,
                                                 b_hh_b, out);
    fc_kernel<<<dim3(kH / 8, kB), 256>>>(fc_W, fc_b, out);
}